// round 3
// baseline (speedup 1.0000x reference)
#include <cuda_runtime.h>
#include <cstdint>

#define DI __device__ __forceinline__

namespace {

constexpr int kT = 28;
constexpr int kI = 28;
constexpr int kH = 128;
constexpr int kC = 10;
constexpr int WARPS = 6;
constexpr int THREADS = WARPS * 32;          // 192
constexpr int TILES = 32768 / 16;            // 2048 warp-tiles
constexpr int GRID = (TILES + WARPS - 1) / WARPS;  // 342

// SMEM byte offsets
constexpr unsigned OFF_W = 0;                 // [16kt][16nt][32lane][2] tf32 = 65536
constexpr unsigned OFF_U = 65536;             // [4kt][16nt][32][2]          = 16384
constexpr unsigned OFF_V = 65536 + 16384;     // [16kt][2nt][32][2]          = 8192
constexpr unsigned OFF_X = 65536 + 16384 + 8192;  // 96 rows * 144 B         = 13824
constexpr unsigned SMEM_TOTAL = OFF_X + 96 * 144; // 103936 (<= 113792 for 2 CTA/SM)

DI unsigned f2tf32(float f) {
  unsigned u;
  asm("cvt.rna.tf32.f32 %0, %1;" : "=r"(u) : "f"(f));
  return u;
}

// accurate tanh: 1 - 2/(exp(2z)+1) via ex2.approx + rcp.approx (~1e-6 abs, saturates)
DI float tanh_acc(float z) {
  float e, r;
  asm("ex2.approx.f32 %0, %1;" : "=f"(e) : "f"(z * 2.8853900817779268f));
  asm("rcp.approx.f32 %0, %1;" : "=f"(r) : "f"(e + 1.0f));
  return fmaf(-2.0f, r, 1.0f);
}

// D(m16n8) += A(m16k8, tf32) * B(k8n8, tf32)
DI void mma8u(float* c, const unsigned* a, uint2 b) {
  asm("mma.sync.aligned.m16n8k8.row.col.f32.tf32.tf32.f32 "
      "{%0,%1,%2,%3},{%4,%5,%6,%7},{%8,%9},{%0,%1,%2,%3};"
      : "+f"(c[0]), "+f"(c[1]), "+f"(c[2]), "+f"(c[3])
      : "r"(a[0]), "r"(a[1]), "r"(a[2]), "r"(a[3]), "r"(b.x), "r"(b.y));
}
DI void mma8f(float* c, const float* a, uint2 b) {
  asm("mma.sync.aligned.m16n8k8.row.col.f32.tf32.tf32.f32 "
      "{%0,%1,%2,%3},{%4,%5,%6,%7},{%8,%9},{%0,%1,%2,%3};"
      : "+f"(c[0]), "+f"(c[1]), "+f"(c[2]), "+f"(c[3])
      : "r"(__float_as_uint(a[0])), "r"(__float_as_uint(a[1])),
        "r"(__float_as_uint(a[2])), "r"(__float_as_uint(a[3])),
        "r"(b.x), "r"(b.y));
}

__global__ void __launch_bounds__(THREADS, 2) rnn_kernel(
    const float* __restrict__ x, const float* __restrict__ Uw,
    const float* __restrict__ Ub, const float* __restrict__ Ww,
    const float* __restrict__ Wb, const float* __restrict__ Vw,
    const float* __restrict__ Vb, float* __restrict__ out) {
  extern __shared__ __align__(16) char sm[];
  const int tid = threadIdx.x;
  const int w = tid >> 5, lane = tid & 31;
  const int r = lane >> 2, q = lane & 3;

  // ---- build tf32 B-fragment tables in SMEM (bias folded into U col 28) ----
  for (int idx = tid; idx < kH * kH; idx += THREADS) {  // W^T: B[k][n] = Ww[n*128+k]
    int n = idx >> 7, k = idx & 127;
    int kt = k >> 3, j = (k >> 2) & 1, qq = k & 3;
    int nt = n >> 3, ln = ((n & 7) << 2) | qq;
    *(unsigned*)(sm + OFF_W + (((kt * 16 + nt) * 32 + ln) << 3) + (j << 2)) =
        f2tf32(Ww[idx]);
  }
  for (int idx = tid; idx < kH * 32; idx += THREADS) {  // U^T padded K=32
    int n = idx >> 5, k = idx & 31;
    float v = (k < kI) ? Uw[n * kI + k] : ((k == kI) ? (Ub[n] + Wb[n]) : 0.0f);
    int kt = k >> 3, j = (k >> 2) & 1, qq = k & 3;
    int nt = n >> 3, ln = ((n & 7) << 2) | qq;
    *(unsigned*)(sm + OFF_U + (((kt * 16 + nt) * 32 + ln) << 3) + (j << 2)) =
        f2tf32(v);
  }
  for (int idx = tid; idx < 16 * kH; idx += THREADS) {  // V^T padded N=16
    int n = idx >> 7, k = idx & 127;
    float v = (n < kC) ? Vw[n * kH + k] : 0.0f;
    int kt = k >> 3, j = (k >> 2) & 1, qq = k & 3;
    int nt = n >> 3, ln = ((n & 7) << 2) | qq;
    *(unsigned*)(sm + OFF_V + (((kt * 2 + nt) * 32 + ln) << 3) + (j << 2)) =
        f2tf32(v);
  }
  __syncthreads();

  const int g = blockIdx.x * WARPS + w;  // global warp-tile (16 batch rows)
  if (g >= TILES) return;                // no barriers after this point

  // x staging roles: 2 lanes per row, 14 floats each
  const int rl = lane >> 1, h = lane & 1;
  const float* xg = x + (long)(g * 16 + rl) * (kT * kI) + h * 14;
  char* xw = sm + OFF_X + (w * 16 + rl) * 144 + h * 56;   // store base
  const char* xr = sm + OFF_X + (w * 16 + r) * 144;       // frag-read base

  {  // t = 0 tile + pad cols (col28 = 1.0 bias driver, 29..31 = 0)
    const float2* p = (const float2*)xg;
    float2 pf[7];
#pragma unroll
    for (int i = 0; i < 7; i++) pf[i] = p[i];
#pragma unroll
    for (int i = 0; i < 7; i++) ((float2*)xw)[i] = pf[i];
    if (h == 1)
      *(float4*)(sm + OFF_X + (w * 16 + rl) * 144 + 112) =
          make_float4(1.0f, 0.0f, 0.0f, 0.0f);
  }
  __syncwarp();

  float FA[16][4], FB[16][4];  // ping-pong: A-fragments / C-accumulators
  const unsigned src0 = (unsigned)((lane & ~3) | (q >> 1));
  const unsigned src2 = src0 + 2;
  const bool qodd = (q & 1) != 0;

  // C(m16n8 tile) -> tanh -> tf32 -> A(m16k8 frag), in place, warp-local
  auto transform = [&](float(&C)[16][4]) {
#pragma unroll
    for (int gg = 0; gg < 16; gg++) {
      unsigned v0 = f2tf32(tanh_acc(C[gg][0]));
      unsigned v1 = f2tf32(tanh_acc(C[gg][1]));
      unsigned v2 = f2tf32(tanh_acc(C[gg][2]));
      unsigned v3 = f2tf32(tanh_acc(C[gg][3]));
      unsigned t0, t1, a0, a1, a2, a3;
      t0 = __shfl_sync(0xffffffffu, v0, src0);
      t1 = __shfl_sync(0xffffffffu, v1, src0);
      a0 = qodd ? t1 : t0;
      t0 = __shfl_sync(0xffffffffu, v0, src2);
      t1 = __shfl_sync(0xffffffffu, v1, src2);
      a2 = qodd ? t1 : t0;
      t0 = __shfl_sync(0xffffffffu, v2, src0);
      t1 = __shfl_sync(0xffffffffu, v3, src0);
      a1 = qodd ? t1 : t0;
      t0 = __shfl_sync(0xffffffffu, v2, src2);
      t1 = __shfl_sync(0xffffffffu, v3, src2);
      a3 = qodd ? t1 : t0;
      C[gg][0] = __uint_as_float(a0);
      C[gg][1] = __uint_as_float(a1);
      C[gg][2] = __uint_as_float(a2);
      C[gg][3] = __uint_as_float(a3);
    }
  };

  auto step = [&](float(&A)[16][4], float(&C)[16][4], int t) {
    // x fragments for this step (bank-conflict-free: row pitch 36 floats)
    unsigned xf[4][4];
#pragma unroll
    for (int kt = 0; kt < 4; kt++) {
      xf[kt][0] = *(const unsigned*)(xr + (kt * 8 + q) * 4);
      xf[kt][1] = *(const unsigned*)(xr + 8 * 144 + (kt * 8 + q) * 4);
      xf[kt][2] = *(const unsigned*)(xr + (kt * 8 + q + 4) * 4);
      xf[kt][3] = *(const unsigned*)(xr + 8 * 144 + (kt * 8 + q + 4) * 4);
    }
#pragma unroll
    for (int nt = 0; nt < 16; nt++) {
      C[nt][0] = 0.0f; C[nt][1] = 0.0f; C[nt][2] = 0.0f; C[nt][3] = 0.0f;
    }
    // U part: C += x_t @ U^T (+ biases via col 28)
#pragma unroll
    for (int kt = 0; kt < 4; kt++) {
      const uint2* bb = (const uint2*)(sm + OFF_U) + kt * 512 + lane;
#pragma unroll
      for (int nt = 0; nt < 16; nt++) mma8u(C[nt], xf[kt], bb[nt * 32]);
    }
    // prefetch x_{t+1} while W-MMAs run (xf regs are dead now)
    float2 pf[7];
    if (t + 1 < kT) {
      const float2* p = (const float2*)(xg + (t + 1) * kI);
#pragma unroll
      for (int i = 0; i < 7; i++) pf[i] = p[i];
    }
    // W part: C += S_{t-1} @ W^T
    if (t > 0) {
#pragma unroll
      for (int kt = 0; kt < 16; kt++) {
        const uint2* bb = (const uint2*)(sm + OFF_W) + kt * 512 + lane;
#pragma unroll
        for (int nt = 0; nt < 16; nt++) mma8f(C[nt], A[kt], bb[nt * 32]);
      }
    }
    transform(C);  // C now holds A-fragments of S_t
    if (t + 1 < kT) {
      __syncwarp();  // all lanes' xf LDS done before overwrite
#pragma unroll
      for (int i = 0; i < 7; i++) ((float2*)xw)[i] = pf[i];
      __syncwarp();
    }
  };

#pragma unroll 1
  for (int t = 0; t < kT; t += 2) {
    step(FA, FB, t);      // writes S_t frags into FB
    step(FB, FA, t + 1);  // writes S_{t+1} frags into FA
  }
  // final state fragments in FA -> out = S @ V^T + V_b  (N padded to 16)
  float o0[4] = {0, 0, 0, 0}, o1[4] = {0, 0, 0, 0};
#pragma unroll
  for (int kt = 0; kt < 16; kt++) {
    const uint2* bb = (const uint2*)(sm + OFF_V) + kt * 64 + lane;
    mma8f(o0, FA[kt], bb[0]);
    mma8f(o1, FA[kt], bb[32]);
  }
  const float vb0 = __ldg(Vb + 2 * q), vb1 = __ldg(Vb + 2 * q + 1);
  const int row0 = g * 16 + r;
  *(float2*)(out + row0 * 10 + 2 * q) = make_float2(o0[0] + vb0, o0[1] + vb1);
  *(float2*)(out + (row0 + 8) * 10 + 2 * q) =
      make_float2(o0[2] + vb0, o0[3] + vb1);
  if (q == 0) {
    const float vb8 = __ldg(Vb + 8), vb9 = __ldg(Vb + 9);
    *(float2*)(out + row0 * 10 + 8) = make_float2(o1[0] + vb8, o1[1] + vb9);
    *(float2*)(out + (row0 + 8) * 10 + 8) =
        make_float2(o1[2] + vb8, o1[3] + vb9);
  }
}

}  // namespace

extern "C" void kernel_launch(void* const* d_in, const int* in_sizes, int n_in,
                              void* d_out, int out_size) {
  (void)in_sizes; (void)n_in; (void)out_size;
  cudaFuncSetAttribute(rnn_kernel, cudaFuncAttributeMaxDynamicSharedMemorySize,
                       SMEM_TOTAL);
  rnn_kernel<<<GRID, THREADS, SMEM_TOTAL>>>(
      (const float*)d_in[0], (const float*)d_in[1], (const float*)d_in[2],
      (const float*)d_in[3], (const float*)d_in[4], (const float*)d_in[5],
      (const float*)d_in[6], (float*)d_out);
}

// round 4
// speedup vs baseline: 1.9619x; 1.9619x over previous
#include <cuda_runtime.h>
#include <cuda_fp16.h>
#include <cstdint>

#define DI __device__ __forceinline__

namespace {

constexpr int kT = 28;
constexpr int kI = 28;
constexpr int kH = 128;
constexpr int kC = 10;
constexpr int WARPS = 5;
constexpr int THREADS = WARPS * 32;                 // 160
constexpr int TILES = 32768 / 16;                   // 2048 warp-tiles
constexpr int GRID = (TILES + WARPS - 1) / WARPS;   // 410

// SMEM byte offsets (fp16 B-fragment tables)
constexpr unsigned OFF_W = 0;                   // [8kt][16nt][32 lane][2 reg*4B] = 32768
constexpr unsigned OFF_U = 32768;               // [2kt][16nt][32][8]            = 8192
constexpr unsigned OFF_V = 32768 + 8192;        // [8kt][2nt][32][8]             = 4096
constexpr unsigned SMEM_TOTAL = OFF_V + 4096;   // 45056 -> 3 CTAs/SM

// accurate tanh: 1 - 2/(exp(2z)+1) via ex2.approx + rcp.approx (~1e-6 abs)
DI float tanh_acc(float z) {
  float e, r;
  asm("ex2.approx.f32 %0, %1;" : "=f"(e) : "f"(z * 2.8853900817779268f));
  asm("rcp.approx.f32 %0, %1;" : "=f"(r) : "f"(e + 1.0f));
  return fmaf(-2.0f, r, 1.0f);
}

// pack two fp32 -> fp16x2 (lo = a, hi = b)
DI unsigned packh(float a, float b) {
  unsigned d;
  asm("cvt.rn.f16x2.f32 %0, %1, %2;" : "=r"(d) : "f"(b), "f"(a));
  return d;
}
DI unsigned packh2(float2 v) { return packh(v.x, v.y); }

// C += A(m16k16 f16) * B(k16n8 f16), fp32 accumulate
DI void mma16(float* c, const unsigned* a, uint2 b) {
  asm("mma.sync.aligned.m16n8k16.row.col.f32.f16.f16.f32 "
      "{%0,%1,%2,%3},{%4,%5,%6,%7},{%8,%9},{%0,%1,%2,%3};"
      : "+f"(c[0]), "+f"(c[1]), "+f"(c[2]), "+f"(c[3])
      : "r"(a[0]), "r"(a[1]), "r"(a[2]), "r"(a[3]), "r"(b.x), "r"(b.y));
}
// C = A*B (zero accumulator — saves per-step C zeroing)
DI void mma16z(float* c, const unsigned* a, uint2 b) {
  asm("mma.sync.aligned.m16n8k16.row.col.f32.f16.f16.f32 "
      "{%0,%1,%2,%3},{%4,%5,%6,%7},{%8,%9},{%10,%10,%10,%10};"
      : "=f"(c[0]), "=f"(c[1]), "=f"(c[2]), "=f"(c[3])
      : "r"(a[0]), "r"(a[1]), "r"(a[2]), "r"(a[3]), "r"(b.x), "r"(b.y),
        "f"(0.0f));
}

__global__ void __launch_bounds__(THREADS, 3) rnn_kernel(
    const float* __restrict__ x, const float* __restrict__ Uw,
    const float* __restrict__ Ub, const float* __restrict__ Ww,
    const float* __restrict__ Wb, const float* __restrict__ Vw,
    const float* __restrict__ Vb, float* __restrict__ out) {
  extern __shared__ __align__(16) char sm[];
  const int tid = threadIdx.x;
  const int w = tid >> 5, lane = tid & 31;
  const int r = lane >> 2, q = lane & 3;

  // ---- build fp16 B-fragment tables (m16n8k16 layout), bias folded in U ----
  // element (n,k): kt=k>>4, kk=k&15, nt=n>>3, rr=n&7; lane=rr*4+((kk>>1)&3);
  // reg j=(kk>>3)&1 (b0/b1), half h=kk&1.
  for (int idx = tid; idx < kH * kH; idx += THREADS) {  // W^T[k][n]=Ww[n*128+k]
    int n = idx >> 7, k = idx & 127;
    int kt = k >> 4, kk = k & 15, nt = n >> 3, rr = n & 7;
    unsigned off = OFF_W + (((kt * 16 + nt) * 32 + rr * 4 + ((kk >> 1) & 3)) << 3) +
                   ((kk >> 3) & 1) * 4 + (kk & 1) * 2;
    *(__half*)(sm + off) = __float2half_rn(Ww[idx]);
  }
  for (int idx = tid; idx < kH * 32; idx += THREADS) {  // U^T padded K=32
    int n = idx >> 5, k = idx & 31;
    float v = (k < kI) ? Uw[n * kI + k] : ((k == kI) ? (Ub[n] + Wb[n]) : 0.0f);
    int kt = k >> 4, kk = k & 15, nt = n >> 3, rr = n & 7;
    unsigned off = OFF_U + (((kt * 16 + nt) * 32 + rr * 4 + ((kk >> 1) & 3)) << 3) +
                   ((kk >> 3) & 1) * 4 + (kk & 1) * 2;
    *(__half*)(sm + off) = __float2half_rn(v);
  }
  for (int idx = tid; idx < 16 * kH; idx += THREADS) {  // V^T padded N=16
    int n = idx >> 7, k = idx & 127;
    float v = (n < kC) ? Vw[n * kH + k] : 0.0f;
    int kt = k >> 4, kk = k & 15, nt = n >> 3, rr = n & 7;
    unsigned off = OFF_V + (((kt * 2 + nt) * 32 + rr * 4 + ((kk >> 1) & 3)) << 3) +
                   ((kk >> 3) & 1) * 4 + (kk & 1) * 2;
    *(__half*)(sm + off) = __float2half_rn(v);
  }
  __syncthreads();

  const int g = blockIdx.x * WARPS + w;  // global warp-tile (16 batch rows)
  if (g >= TILES) return;                // no CTA-wide sync past this point

  // x rows for this lane's fragments: rows g*16+r and g*16+r+8
  const float* xb0 = x + (long)(g * 16 + r) * (kT * kI);
  const float* xb1 = xb0 + 8 * (kT * kI);

  // raw x loads for step t: chunks at cols {2q, 8+2q, 16+2q, 24+2q(pred)} x 2 rows
  float2 xraw[8];
  auto ldx = [&](int t) {
    const float* p0 = xb0 + t * kI;
    const float* p1 = xb1 + t * kI;
    xraw[0] = *(const float2*)(p0 + 2 * q);
    xraw[1] = *(const float2*)(p0 + 8 + 2 * q);
    xraw[2] = *(const float2*)(p0 + 16 + 2 * q);
    xraw[4] = *(const float2*)(p1 + 2 * q);
    xraw[5] = *(const float2*)(p1 + 8 + 2 * q);
    xraw[6] = *(const float2*)(p1 + 16 + 2 * q);
    if (q < 2) {
      xraw[3] = *(const float2*)(p0 + 24 + 2 * q);
      xraw[7] = *(const float2*)(p1 + 24 + 2 * q);
    }
  };
  unsigned xf[2][4];  // A-fragments of [x_t | 1 | 0pad], 2 k-tiles
  auto cvtx = [&] {
    xf[0][0] = packh2(xraw[0]); xf[0][1] = packh2(xraw[4]);
    xf[0][2] = packh2(xraw[1]); xf[0][3] = packh2(xraw[5]);
    xf[1][0] = packh2(xraw[2]); xf[1][1] = packh2(xraw[6]);
    const unsigned cpad = (q == 2) ? 0x00003C00u : 0u;  // cols 28..31 = 1,0,0,0
    xf[1][2] = (q < 2) ? packh2(xraw[3]) : cpad;
    xf[1][3] = (q < 2) ? packh2(xraw[7]) : cpad;
  };

  ldx(0);
  cvtx();

  unsigned A[8][4];   // state S fragments (fp16x2), overwritten in place
  float C[16][4];     // fp32 accumulators, one m16n8 tile per nt

#pragma unroll 1
  for (int t = 0; t < kT; t++) {
    // U part: C = x_t @ U^T (+ biases via col 28); kt=0 initializes C
    {
      const uint2* b0 = (const uint2*)(sm + OFF_U) + lane;
      const uint2* b1 = b0 + 512;
#pragma unroll
      for (int nt = 0; nt < 16; nt++) mma16z(C[nt], xf[0], b0[nt * 32]);
#pragma unroll
      for (int nt = 0; nt < 16; nt++) mma16(C[nt], xf[1], b1[nt * 32]);
    }
    // prefetch x_{t+1} raw under the W MMAs
    if (t + 1 < kT) ldx(t + 1);
    // W part: C += S_{t-1} @ W^T
    if (t > 0) {
#pragma unroll
      for (int kt = 0; kt < 8; kt++) {
        const uint2* bb = (const uint2*)(sm + OFF_W) + kt * 512 + lane;
#pragma unroll
        for (int nt = 0; nt < 16; nt++) mma16(C[nt], A[kt], bb[nt * 32]);
      }
    }
    // transform: S_t = tanh(C) -> fp16 A-fragments (lane-identical remap, no shuffles)
#pragma unroll
    for (int nt = 0; nt < 16; nt++) {
      unsigned h0 = packh(tanh_acc(C[nt][0]), tanh_acc(C[nt][1]));
      unsigned h1 = packh(tanh_acc(C[nt][2]), tanh_acc(C[nt][3]));
      A[nt >> 1][(nt & 1) * 2 + 0] = h0;
      A[nt >> 1][(nt & 1) * 2 + 1] = h1;
    }
    if (t + 1 < kT) cvtx();
  }

  // output: out = S @ V^T + V_b (N padded to 16)
  float o0[4], o1[4];
  {
    const uint2* bb = (const uint2*)(sm + OFF_V) + lane;
    mma16z(o0, A[0], bb[0]);
    mma16z(o1, A[0], bb[32]);
#pragma unroll
    for (int kt = 1; kt < 8; kt++) {
      mma16(o0, A[kt], bb[kt * 64]);
      mma16(o1, A[kt], bb[kt * 64 + 32]);
    }
  }
  const float vb0 = __ldg(Vb + 2 * q), vb1 = __ldg(Vb + 2 * q + 1);
  const int row0 = g * 16 + r;
  *(float2*)(out + row0 * kC + 2 * q) = make_float2(o0[0] + vb0, o0[1] + vb1);
  *(float2*)(out + (row0 + 8) * kC + 2 * q) =
      make_float2(o0[2] + vb0, o0[3] + vb1);
  if (q == 0) {
    const float vb8 = __ldg(Vb + 8), vb9 = __ldg(Vb + 9);
    *(float2*)(out + row0 * kC + 8) = make_float2(o1[0] + vb8, o1[1] + vb9);
    *(float2*)(out + (row0 + 8) * kC + 8) =
        make_float2(o1[2] + vb8, o1[3] + vb9);
  }
}

}  // namespace

extern "C" void kernel_launch(void* const* d_in, const int* in_sizes, int n_in,
                              void* d_out, int out_size) {
  (void)in_sizes; (void)n_in; (void)out_size;
  cudaFuncSetAttribute(rnn_kernel, cudaFuncAttributeMaxDynamicSharedMemorySize,
                       SMEM_TOTAL);
  rnn_kernel<<<GRID, THREADS, SMEM_TOTAL>>>(
      (const float*)d_in[0], (const float*)d_in[1], (const float*)d_in[2],
      (const float*)d_in[3], (const float*)d_in[4], (const float*)d_in[5],
      (const float*)d_in[6], (float*)d_out);
}

// round 6
// speedup vs baseline: 2.3313x; 1.1883x over previous
#include <cuda_runtime.h>
#include <cuda_fp16.h>
#include <cstdint>

#define DI __device__ __forceinline__

namespace {

constexpr int kT = 28;
constexpr int kI = 28;
constexpr int kH = 128;
constexpr int kC = 10;
constexpr int WARPS = 5;
constexpr int THREADS = WARPS * 32;                 // 160
constexpr int TILES = 32768 / 16;                   // 2048 warp-tiles
constexpr int GRID = (TILES + WARPS - 1) / WARPS;   // 410

// SMEM: paired-B fragment tables. One uint4 per lane per (kt, nt-pair)
// = B fragments for two consecutive n-tiles -> one LDS.128 feeds two MMAs.
constexpr unsigned OFF_W = 0;                   // [8kt][8ntp][32 lane][16B] = 32768
constexpr unsigned OFF_U = 32768;               // [2kt][8ntp][32][16B]     = 8192
constexpr unsigned OFF_V = 32768 + 8192;        // [8kt][1ntp][32][16B]     = 4096
constexpr unsigned SMEM_TOTAL = OFF_V + 4096;   // 45056 -> 3 CTAs/SM

DI float th(float z) {  // HW tanh (single MUFU)
  float r;
  asm("tanh.approx.f32 %0, %1;" : "=f"(r) : "f"(z));
  return r;
}

// pack two fp32 -> fp16x2 (lo = a, hi = b)
DI unsigned packh(float a, float b) {
  unsigned d;
  asm("cvt.rn.f16x2.f32 %0, %1, %2;" : "=r"(d) : "f"(b), "f"(a));
  return d;
}
DI unsigned packh2(float2 v) { return packh(v.x, v.y); }

// C += A(m16k16 f16) * B(k16n8 f16), fp32 accumulate
DI void mma16(float* c, const unsigned* a, unsigned bx, unsigned by) {
  asm("mma.sync.aligned.m16n8k16.row.col.f32.f16.f16.f32 "
      "{%0,%1,%2,%3},{%4,%5,%6,%7},{%8,%9},{%0,%1,%2,%3};"
      : "+f"(c[0]), "+f"(c[1]), "+f"(c[2]), "+f"(c[3])
      : "r"(a[0]), "r"(a[1]), "r"(a[2]), "r"(a[3]), "r"(bx), "r"(by));
}
// C = A*B (zero accumulator)
DI void mma16z(float* c, const unsigned* a, unsigned bx, unsigned by) {
  asm("mma.sync.aligned.m16n8k16.row.col.f32.f16.f16.f32 "
      "{%0,%1,%2,%3},{%4,%5,%6,%7},{%8,%9},{%10,%10,%10,%10};"
      : "=f"(c[0]), "=f"(c[1]), "=f"(c[2]), "=f"(c[3])
      : "r"(a[0]), "r"(a[1]), "r"(a[2]), "r"(a[3]), "r"(bx), "r"(by),
        "f"(0.0f));
}

// B element (n,k) -> byte offset inside a paired table with `ntpn` nt-pairs
// (kt stride = ntpn * 32 uint4). W: ntpn=8, U: ntpn=8, V: ntpn=1.
DI unsigned bpos(int n, int k, int ntpn) {
  int kt = k >> 4, kk = k & 15, nt = n >> 3, rr = n & 7;
  int ntp = nt >> 1, sel = nt & 1;
  int ln = rr * 4 + ((kk >> 1) & 3);
  return (unsigned)((((kt * ntpn + ntp) * 32 + ln) << 4) + sel * 8 +
                    ((kk >> 3) & 1) * 4 + (kk & 1) * 2);
}

__global__ void __launch_bounds__(THREADS, 3) rnn_kernel(
    const float* __restrict__ x, const float* __restrict__ Uw,
    const float* __restrict__ Ub, const float* __restrict__ Ww,
    const float* __restrict__ Wb, const float* __restrict__ Vw,
    const float* __restrict__ Vb, float* __restrict__ out) {
  extern __shared__ __align__(16) char sm[];
  const int tid = threadIdx.x;
  const int w = tid >> 5, lane = tid & 31;
  const int r = lane >> 2, q = lane & 3;

  // ---- build fp16 paired-B fragment tables, biases folded into U col 28 ----
  for (int idx = tid; idx < kH * kH; idx += THREADS) {  // W^T[k][n] = Ww[n*128+k]
    int n = idx >> 7, k = idx & 127;
    *(__half*)(sm + OFF_W + bpos(n, k, 8)) = __float2half_rn(Ww[idx]);
  }
  for (int idx = tid; idx < kH * 32; idx += THREADS) {  // U^T padded K=32
    int n = idx >> 5, k = idx & 31;
    float v = (k < kI) ? Uw[n * kI + k] : ((k == kI) ? (Ub[n] + Wb[n]) : 0.0f);
    *(__half*)(sm + OFF_U + bpos(n, k, 8)) = __float2half_rn(v);
  }
  for (int idx = tid; idx < 16 * kH; idx += THREADS) {  // V^T padded N=16
    int n = idx >> 7, k = idx & 127;
    float v = (n < kC) ? Vw[n * kH + k] : 0.0f;
    *(__half*)(sm + OFF_V + bpos(n, k, 1)) = __float2half_rn(v);
  }
  __syncthreads();

  const int g = blockIdx.x * WARPS + w;  // global warp-tile (16 batch rows)
  if (g >= TILES) return;                // no CTA-wide sync past this point

  // x rows for this lane's A-fragments: rows g*16+r and g*16+r+8
  const float* xb0 = x + (long)(g * 16 + r) * (kT * kI);
  const float* xb1 = xb0 + 8 * (kT * kI);

  float2 xraw[8];
  auto ldx = [&](int t) {
    const float* p0 = xb0 + t * kI;
    const float* p1 = xb1 + t * kI;
    xraw[0] = *(const float2*)(p0 + 2 * q);
    xraw[1] = *(const float2*)(p0 + 8 + 2 * q);
    xraw[2] = *(const float2*)(p0 + 16 + 2 * q);
    xraw[4] = *(const float2*)(p1 + 2 * q);
    xraw[5] = *(const float2*)(p1 + 8 + 2 * q);
    xraw[6] = *(const float2*)(p1 + 16 + 2 * q);
    if (q < 2) {
      xraw[3] = *(const float2*)(p0 + 24 + 2 * q);
      xraw[7] = *(const float2*)(p1 + 24 + 2 * q);
    }
  };
  unsigned xf[2][4];  // A-fragments of [x_t | 1 | 0pad]
  auto cvtx = [&] {
    xf[0][0] = packh2(xraw[0]); xf[0][1] = packh2(xraw[4]);
    xf[0][2] = packh2(xraw[1]); xf[0][3] = packh2(xraw[5]);
    xf[1][0] = packh2(xraw[2]); xf[1][1] = packh2(xraw[6]);
    const unsigned cpad = (q == 2) ? 0x00003C00u : 0u;  // cols 28..31 = 1,0,0,0
    xf[1][2] = (q < 2) ? packh2(xraw[3]) : cpad;
    xf[1][3] = (q < 2) ? packh2(xraw[7]) : cpad;
  };

  ldx(0);
  cvtx();

  unsigned A[8][4];   // state S fragments (fp16x2)
  float C[16][4];     // fp32 accumulators, one m16n8 tile per nt

#pragma unroll 1
  for (int t = 0; t < kT; t++) {
    // U part: C = x_t @ U^T (+ biases); kt=0 initializes C
    {
      const uint4* b0 = (const uint4*)(sm + OFF_U) + lane;
      const uint4* b1 = b0 + 256;
#pragma unroll
      for (int i = 0; i < 8; i++) {
        uint4 bb = b0[i * 32];
        mma16z(C[2 * i], xf[0], bb.x, bb.y);
        mma16z(C[2 * i + 1], xf[0], bb.z, bb.w);
      }
#pragma unroll
      for (int i = 0; i < 8; i++) {
        uint4 bb = b1[i * 32];
        mma16(C[2 * i], xf[1], bb.x, bb.y);
        mma16(C[2 * i + 1], xf[1], bb.z, bb.w);
      }
    }
    // prefetch x_{t+1} under the W MMAs
    if (t + 1 < kT) ldx(t + 1);
    // W part: C += S_{t-1} @ W^T
    if (t > 0) {
#pragma unroll
      for (int kt = 0; kt < 8; kt++) {
        const uint4* bb = (const uint4*)(sm + OFF_W) + kt * 256 + lane;
#pragma unroll
        for (int i = 0; i < 8; i++) {
          uint4 b = bb[i * 32];
          mma16(C[2 * i], A[kt], b.x, b.y);
          mma16(C[2 * i + 1], A[kt], b.z, b.w);
        }
      }
    }
    // transform: S_t = tanh(C) -> fp16 A-fragments (lane-identical remap)
#pragma unroll
    for (int i = 0; i < 8; i++) {
      A[i][0] = packh(th(C[2 * i][0]), th(C[2 * i][1]));
      A[i][1] = packh(th(C[2 * i][2]), th(C[2 * i][3]));
      A[i][2] = packh(th(C[2 * i + 1][0]), th(C[2 * i + 1][1]));
      A[i][3] = packh(th(C[2 * i + 1][2]), th(C[2 * i + 1][3]));
    }
    if (t + 1 < kT) cvtx();
  }

  // output: out = S @ V^T + V_b (N padded to 16 = one nt-pair; kt stride 32)
  float o0[4], o1[4];
  {
    const uint4* bb = (const uint4*)(sm + OFF_V) + lane;
    uint4 b = bb[0];
    mma16z(o0, A[0], b.x, b.y);
    mma16z(o1, A[0], b.z, b.w);
#pragma unroll
    for (int kt = 1; kt < 8; kt++) {
      b = bb[kt * 32];
      mma16(o0, A[kt], b.x, b.y);
      mma16(o1, A[kt], b.z, b.w);
    }
  }
  const float vb0 = __ldg(Vb + 2 * q), vb1 = __ldg(Vb + 2 * q + 1);
  const int row0 = g * 16 + r;
  *(float2*)(out + row0 * kC + 2 * q) = make_float2(o0[0] + vb0, o0[1] + vb1);
  *(float2*)(out + (row0 + 8) * kC + 2 * q) =
      make_float2(o0[2] + vb0, o0[3] + vb1);
  if (q == 0) {
    const float vb8 = __ldg(Vb + 8), vb9 = __ldg(Vb + 9);
    *(float2*)(out + row0 * kC + 8) = make_float2(o1[0] + vb8, o1[1] + vb9);
    *(float2*)(out + (row0 + 8) * kC + 8) =
        make_float2(o1[2] + vb8, o1[3] + vb9);
  }
}

}  // namespace

extern "C" void kernel_launch(void* const* d_in, const int* in_sizes, int n_in,
                              void* d_out, int out_size) {
  (void)in_sizes; (void)n_in; (void)out_size;
  cudaFuncSetAttribute(rnn_kernel, cudaFuncAttributeMaxDynamicSharedMemorySize,
                       SMEM_TOTAL);
  rnn_kernel<<<GRID, THREADS, SMEM_TOTAL>>>(
      (const float*)d_in[0], (const float*)d_in[1], (const float*)d_in[2],
      (const float*)d_in[3], (const float*)d_in[4], (const float*)d_in[5],
      (const float*)d_in[6], (float*)d_out);
}